// round 9
// baseline (speedup 1.0000x reference)
#include <cuda_runtime.h>
#include <cstdint>

#define DIM 1024
#define NH 16
#define HD 64
#define TSEQ 2048
#define BT 4096          // B * T
#define GSTR 20          // gemm smem stride (words): conflict-free rows for ldmatrix
#define FSTR 68          // attention smem stride (words)
#define QT 128           // attention query-tile rows

// Scratch (static device arrays; allocation in kernel_launch is forbidden)
__device__ float g_h[BT * DIM];
__device__ float g_q[BT * DIM];
__device__ float g_k[BT * DIM];
__device__ float g_v[BT * DIM];
__device__ float g_att[BT * DIM];

// ---------------------------------------------------------------------------
// LayerNorm: one block per row of x [4096, 1024]
// ---------------------------------------------------------------------------
__global__ void ln_kernel(const float* __restrict__ x,
                          const float* __restrict__ gamma,
                          const float* __restrict__ beta,
                          float* __restrict__ out) {
    int row = blockIdx.x;
    const float* xr = x + (size_t)row * DIM;
    float* orow = out + (size_t)row * DIM;
    int t = threadIdx.x;

    float v[4];
    float sum = 0.f, sq = 0.f;
#pragma unroll
    for (int i = 0; i < 4; i++) {
        float val = xr[t + i * 256];
        v[i] = val;
        sum += val;
        sq += val * val;
    }
#pragma unroll
    for (int o = 16; o > 0; o >>= 1) {
        sum += __shfl_xor_sync(0xffffffffu, sum, o);
        sq  += __shfl_xor_sync(0xffffffffu, sq, o);
    }
    __shared__ float s1[8], s2[8];
    if ((t & 31) == 0) { s1[t >> 5] = sum; s2[t >> 5] = sq; }
    __syncthreads();
    float tot = 0.f, totq = 0.f;
#pragma unroll
    for (int i = 0; i < 8; i++) { tot += s1[i]; totq += s2[i]; }
    float mu   = tot * (1.0f / DIM);
    float var  = totq * (1.0f / DIM) - mu * mu;
    float rstd = rsqrtf(var + 1e-5f);
#pragma unroll
    for (int i = 0; i < 4; i++) {
        int c = t + i * 256;
        orow[c] = (v[i] - mu) * rstd * gamma[c] + beta[c];
    }
}

// ---------------------------------------------------------------------------
// tf32 helpers
// ---------------------------------------------------------------------------
__device__ __forceinline__ uint32_t f2tf(float x) {
    uint32_t y;
    asm("cvt.rna.tf32.f32 %0, %1;" : "=r"(y) : "f"(x));
    return y;
}

__device__ __forceinline__ void mma_tf32(float* c, const uint32_t* a,
                                         const uint32_t* b) {
    asm volatile(
        "mma.sync.aligned.m16n8k8.row.col.f32.tf32.tf32.f32 "
        "{%0,%1,%2,%3}, {%4,%5,%6,%7}, {%8,%9}, {%0,%1,%2,%3};\n"
        : "+f"(c[0]), "+f"(c[1]), "+f"(c[2]), "+f"(c[3])
        : "r"(a[0]), "r"(a[1]), "r"(a[2]), "r"(a[3]), "r"(b[0]), "r"(b[1]));
}

__device__ __forceinline__ void ldsm_x4(uint32_t& r0, uint32_t& r1,
                                        uint32_t& r2, uint32_t& r3,
                                        uint32_t addr) {
    asm volatile(
        "ldmatrix.sync.aligned.m8n8.x4.shared.b16 {%0,%1,%2,%3}, [%4];"
        : "=r"(r0), "=r"(r1), "=r"(r2), "=r"(r3) : "r"(addr));
}

// ---------------------------------------------------------------------------
// tf32 GEMM NT, 128x128 block / 4 warps of 64x64 / ldmatrix fragment loads.
// C[m][n] = sum_k A[m][k]*B[n][k] + bias[n].  BK=16, 2-stage double buffer.
// Warp grid 2x2: wm=(w&1)*64, wn=(w>>1)*64. Per warp: mi=4 (m16), ni=8 (n8).
// ---------------------------------------------------------------------------
__device__ __forceinline__ void gemm_tf32_body(const float* __restrict__ A,
                                               const float* __restrict__ B,
                                               const float* __restrict__ bias,
                                               float* __restrict__ C,
                                               int M, int N, int K) {
    __shared__ uint32_t As[2][128 * GSTR];
    __shared__ uint32_t Bs[2][128 * GSTR];

    int tid = threadIdx.x;
    int bm = blockIdx.y * 128;
    int bn = blockIdx.x * 128;
    int w = tid >> 5, lane = tid & 31;
    int wm = (w & 1) * 64;
    int wn = (w >> 1) * 64;
    int lq = lane >> 2;
    int lrm = lane & 3;

    // Loader mapping: thread tid owns row tid (A and B), 16 floats along k
    const float* Ap = A + (size_t)(bm + tid) * K;
    const float* Bp = B + (size_t)(bn + tid) * K;

    // ldmatrix lane addressing
    int g = lane >> 3;            // tile group 0..3
    int lr8 = lane & 7;           // row within 8x8 tile
    uint32_t aBase = (uint32_t)__cvta_generic_to_shared(&As[0][0]);
    uint32_t bBase = (uint32_t)__cvta_generic_to_shared(&Bs[0][0]);
    const uint32_t stageBytes = 128 * GSTR * 4;
    // A tiles: g&1 -> +8 rows, g>>1 -> +4 k
    uint32_t aOff = ((uint32_t)(wm + (g & 1) * 8 + lr8) * GSTR + (g >> 1) * 4) * 4;
    // B tiles: g>>1 -> +8 n-rows, g&1 -> +4 k
    uint32_t bOff = ((uint32_t)(wn + (g >> 1) * 8 + lr8) * GSTR + (g & 1) * 4) * 4;

    float acc[4][8][4];
#pragma unroll
    for (int mi = 0; mi < 4; mi++)
#pragma unroll
        for (int ni = 0; ni < 8; ni++)
#pragma unroll
            for (int r = 0; r < 4; r++) acc[mi][ni][r] = 0.f;

    // Prologue: stage 0
    {
        float4 av[4], bv[4];
#pragma unroll
        for (int i = 0; i < 4; i++) {
            av[i] = *(const float4*)(Ap + 4 * i);
            bv[i] = *(const float4*)(Bp + 4 * i);
        }
#pragma unroll
        for (int i = 0; i < 4; i++) {
            uint4 u;
            u.x = f2tf(av[i].x); u.y = f2tf(av[i].y);
            u.z = f2tf(av[i].z); u.w = f2tf(av[i].w);
            *(uint4*)&As[0][tid * GSTR + 4 * i] = u;
            u.x = f2tf(bv[i].x); u.y = f2tf(bv[i].y);
            u.z = f2tf(bv[i].z); u.w = f2tf(bv[i].w);
            *(uint4*)&Bs[0][tid * GSTR + 4 * i] = u;
        }
    }
    __syncthreads();

    int stage = 0;
    for (int k0 = 0; k0 < K; k0 += 16) {
        int nxt = stage ^ 1;
        bool has_next = (k0 + 16) < K;

        float4 av[4], bv[4];
        if (has_next) {
#pragma unroll
            for (int i = 0; i < 4; i++) {
                av[i] = *(const float4*)(Ap + k0 + 16 + 4 * i);
                bv[i] = *(const float4*)(Bp + k0 + 16 + 4 * i);
            }
        }

        uint32_t aS = aBase + stage * stageBytes + aOff;
        uint32_t bS = bBase + stage * stageBytes + bOff;
#pragma unroll
        for (int ks = 0; ks < 16; ks += 8) {
            uint32_t af[4][4];
#pragma unroll
            for (int mi = 0; mi < 4; mi++)
                ldsm_x4(af[mi][0], af[mi][1], af[mi][2], af[mi][3],
                        aS + (uint32_t)(mi * 16 * GSTR + ks) * 4);
            uint32_t bf[8][2];
#pragma unroll
            for (int np = 0; np < 4; np++) {
                uint32_t r0, r1, r2, r3;
                ldsm_x4(r0, r1, r2, r3,
                        bS + (uint32_t)(np * 16 * GSTR + ks) * 4);
                bf[2 * np][0] = r0; bf[2 * np][1] = r1;
                bf[2 * np + 1][0] = r2; bf[2 * np + 1][1] = r3;
            }
#pragma unroll
            for (int mi = 0; mi < 4; mi++)
#pragma unroll
                for (int ni = 0; ni < 8; ni++)
                    mma_tf32(acc[mi][ni], af[mi], bf[ni]);
        }

        if (has_next) {
#pragma unroll
            for (int i = 0; i < 4; i++) {
                uint4 u;
                u.x = f2tf(av[i].x); u.y = f2tf(av[i].y);
                u.z = f2tf(av[i].z); u.w = f2tf(av[i].w);
                *(uint4*)&As[nxt][tid * GSTR + 4 * i] = u;
                u.x = f2tf(bv[i].x); u.y = f2tf(bv[i].y);
                u.z = f2tf(bv[i].z); u.w = f2tf(bv[i].w);
                *(uint4*)&Bs[nxt][tid * GSTR + 4 * i] = u;
            }
            __syncthreads();
        }
        stage = nxt;
    }

#pragma unroll
    for (int mi = 0; mi < 4; mi++) {
#pragma unroll
        for (int ni = 0; ni < 8; ni++) {
            int row0 = bm + wm + mi * 16 + lq;
            int col  = bn + wn + ni * 8 + lrm * 2;
            float2 bb = *(const float2*)&bias[col];
            float2 o0, o1;
            o0.x = acc[mi][ni][0] + bb.x;
            o0.y = acc[mi][ni][1] + bb.y;
            o1.x = acc[mi][ni][2] + bb.x;
            o1.y = acc[mi][ni][3] + bb.y;
            *(float2*)&C[(size_t)row0 * N + col] = o0;
            *(float2*)&C[(size_t)(row0 + 8) * N + col] = o1;
        }
    }
}

__global__ __launch_bounds__(128) void gemm_tf32(const float* __restrict__ A,
                                                 const float* __restrict__ B,
                                                 const float* __restrict__ bias,
                                                 float* __restrict__ C,
                                                 int M, int N, int K) {
    gemm_tf32_body(A, B, bias, C, M, N, K);
}

__global__ __launch_bounds__(128) void gemm_qkv(const float* __restrict__ A,
                                                const float* __restrict__ Wq,
                                                const float* __restrict__ bq,
                                                float* __restrict__ Oq,
                                                const float* __restrict__ Wk,
                                                const float* __restrict__ bk,
                                                float* __restrict__ Ok,
                                                const float* __restrict__ Wv,
                                                const float* __restrict__ bv,
                                                float* __restrict__ Ov,
                                                int M, int N, int K) {
    int z = blockIdx.z;
    const float* W = (z == 0) ? Wq : (z == 1) ? Wk : Wv;
    const float* b = (z == 0) ? bq : (z == 1) ? bk : bv;
    float* O       = (z == 0) ? Oq : (z == 1) ? Ok : Ov;
    gemm_tf32_body(A, W, b, O, M, N, K);
}

// ---------------------------------------------------------------------------
// Tensor-core causal flash attention, 128-row Q tile (frozen from R7).
// ---------------------------------------------------------------------------
__global__ __launch_bounds__(256) void attn_kernel(const float* __restrict__ Q,
                                                   const float* __restrict__ K,
                                                   const float* __restrict__ V,
                                                   float* __restrict__ O) {
    extern __shared__ uint32_t sm[];
    uint32_t* sQ  = sm;                   // QT*FSTR
    uint32_t* sK  = sQ + QT * FSTR;       // 64*FSTR
    uint32_t* sVt = sK + 64 * FSTR;       // 64*FSTR  (sVt[d*FSTR + key])
    uint32_t* sP  = sVt + 64 * FSTR;      // QT*FSTR

    int tid = threadIdx.x;
    int w = tid >> 5, lane = tid & 31;
    int lq = lane >> 2, lrm = lane & 3;
    int rowA = w * 16;
    int qblk = blockIdx.x;
    int h = blockIdx.y;
    int b = blockIdx.z;
    int q0 = qblk * QT;
    size_t base = ((size_t)b * TSEQ) * DIM + h * HD;

    int qlr = tid >> 1;
    int qlc = (tid & 1) * 32;
    int klr = tid & 63;
    int klc = (tid >> 6) * 16;

    {
        const float* src = Q + base + (size_t)(q0 + qlr) * DIM + qlc;
        uint32_t* dst = sQ + qlr * FSTR + qlc;
#pragma unroll
        for (int i = 0; i < 8; i++) {
            float4 t4 = *(const float4*)(src + 4 * i);
            dst[4 * i + 0] = f2tf(t4.x); dst[4 * i + 1] = f2tf(t4.y);
            dst[4 * i + 2] = f2tf(t4.z); dst[4 * i + 3] = f2tf(t4.w);
        }
    }

    float o_frag[8][4];
#pragma unroll
    for (int n = 0; n < 8; n++)
#pragma unroll
        for (int r = 0; r < 4; r++) o_frag[n][r] = 0.f;
    float m0 = -1e30f, m1 = -1e30f, l0 = 0.f, l1 = 0.f;

    int kb_max = 2 * qblk + 1;
    for (int kb = 0; kb <= kb_max; kb++) {
        __syncthreads();
        {
            const float* ksrc = K + base + (size_t)(kb * 64 + klr) * DIM + klc;
            const float* vsrc = V + base + (size_t)(kb * 64 + klr) * DIM + klc;
            uint32_t* kd = sK + klr * FSTR + klc;
#pragma unroll
            for (int i = 0; i < 4; i++) {
                float4 kt = *(const float4*)(ksrc + 4 * i);
                uint4 u;
                u.x = f2tf(kt.x); u.y = f2tf(kt.y);
                u.z = f2tf(kt.z); u.w = f2tf(kt.w);
                *(uint4*)&kd[4 * i] = u;
                float4 vt = *(const float4*)(vsrc + 4 * i);
                sVt[(klc + 4 * i + 0) * FSTR + klr] = f2tf(vt.x);
                sVt[(klc + 4 * i + 1) * FSTR + klr] = f2tf(vt.y);
                sVt[(klc + 4 * i + 2) * FSTR + klr] = f2tf(vt.z);
                sVt[(klc + 4 * i + 3) * FSTR + klr] = f2tf(vt.w);
            }
        }
        __syncthreads();

        if (kb * 64 > q0 + rowA + 15) continue;   // fully masked, warp-uniform

        float s_frag[8][4];
#pragma unroll
        for (int n = 0; n < 8; n++)
#pragma unroll
            for (int r = 0; r < 4; r++) s_frag[n][r] = 0.f;

#pragma unroll
        for (int ks = 0; ks < 64; ks += 8) {
            uint32_t af[4];
            af[0] = sQ[(rowA + lq) * FSTR + ks + lrm];
            af[1] = sQ[(rowA + lq + 8) * FSTR + ks + lrm];
            af[2] = sQ[(rowA + lq) * FSTR + ks + lrm + 4];
            af[3] = sQ[(rowA + lq + 8) * FSTR + ks + lrm + 4];
#pragma unroll
            for (int n = 0; n < 8; n++) {
                uint32_t bf[2];
                bf[0] = sK[(8 * n + lq) * FSTR + ks + lrm];
                bf[1] = sK[(8 * n + lq) * FSTR + ks + lrm + 4];
                mma_tf32(s_frag[n], af, bf);
            }
        }
#pragma unroll
        for (int n = 0; n < 8; n++)
#pragma unroll
            for (int r = 0; r < 4; r++) s_frag[n][r] *= 0.125f;

        if (kb * 64 + 63 > q0 + rowA) {
            int r0 = q0 + rowA + lq, r1 = q0 + rowA + lq + 8;
            int cbase = kb * 64;
#pragma unroll
            for (int n = 0; n < 8; n++) {
                int c = cbase + 8 * n + 2 * lrm;
                if (c > r0)     s_frag[n][0] = -1e30f;
                if (c + 1 > r0) s_frag[n][1] = -1e30f;
                if (c > r1)     s_frag[n][2] = -1e30f;
                if (c + 1 > r1) s_frag[n][3] = -1e30f;
            }
        }

        {
            float mloc0 = -1e30f, mloc1 = -1e30f;
#pragma unroll
            for (int n = 0; n < 8; n++) {
                mloc0 = fmaxf(mloc0, fmaxf(s_frag[n][0], s_frag[n][1]));
                mloc1 = fmaxf(mloc1, fmaxf(s_frag[n][2], s_frag[n][3]));
            }
            mloc0 = fmaxf(mloc0, __shfl_xor_sync(0xffffffffu, mloc0, 1));
            mloc0 = fmaxf(mloc0, __shfl_xor_sync(0xffffffffu, mloc0, 2));
            mloc1 = fmaxf(mloc1, __shfl_xor_sync(0xffffffffu, mloc1, 1));
            mloc1 = fmaxf(mloc1, __shfl_xor_sync(0xffffffffu, mloc1, 2));
            float mn0 = fmaxf(m0, mloc0), mn1 = fmaxf(m1, mloc1);
            float c0 = __expf(m0 - mn0), c1 = __expf(m1 - mn1);
            float ps0 = 0.f, ps1 = 0.f;
#pragma unroll
            for (int n = 0; n < 8; n++) {
                float p0 = __expf(s_frag[n][0] - mn0);
                float p1 = __expf(s_frag[n][1] - mn0);
                float p2 = __expf(s_frag[n][2] - mn1);
                float p3 = __expf(s_frag[n][3] - mn1);
                s_frag[n][0] = p0; s_frag[n][1] = p1;
                s_frag[n][2] = p2; s_frag[n][3] = p3;
                ps0 += p0 + p1; ps1 += p2 + p3;
            }
            ps0 += __shfl_xor_sync(0xffffffffu, ps0, 1);
            ps0 += __shfl_xor_sync(0xffffffffu, ps0, 2);
            ps1 += __shfl_xor_sync(0xffffffffu, ps1, 1);
            ps1 += __shfl_xor_sync(0xffffffffu, ps1, 2);
            l0 = l0 * c0 + ps0; m0 = mn0;
            l1 = l1 * c1 + ps1; m1 = mn1;
#pragma unroll
            for (int n = 0; n < 8; n++) {
                o_frag[n][0] *= c0; o_frag[n][1] *= c0;
                o_frag[n][2] *= c1; o_frag[n][3] *= c1;
            }
        }

#pragma unroll
        for (int n = 0; n < 8; n++) {
            uint2 p01; p01.x = f2tf(s_frag[n][0]); p01.y = f2tf(s_frag[n][1]);
            *(uint2*)&sP[(rowA + lq) * FSTR + 8 * n + 2 * lrm] = p01;
            uint2 p23; p23.x = f2tf(s_frag[n][2]); p23.y = f2tf(s_frag[n][3]);
            *(uint2*)&sP[(rowA + lq + 8) * FSTR + 8 * n + 2 * lrm] = p23;
        }
        __syncwarp();

#pragma unroll
        for (int ks = 0; ks < 64; ks += 8) {
            uint32_t af[4];
            af[0] = sP[(rowA + lq) * FSTR + ks + lrm];
            af[1] = sP[(rowA + lq + 8) * FSTR + ks + lrm];
            af[2] = sP[(rowA + lq) * FSTR + ks + lrm + 4];
            af[3] = sP[(rowA + lq + 8) * FSTR + ks + lrm + 4];
#pragma unroll
            for (int n = 0; n < 8; n++) {
                uint32_t bf[2];
                bf[0] = sVt[(8 * n + lq) * FSTR + ks + lrm];
                bf[1] = sVt[(8 * n + lq) * FSTR + ks + lrm + 4];
                mma_tf32(o_frag[n], af, bf);
            }
        }
    }

    float i0 = 1.0f / l0, i1 = 1.0f / l1;
    float* d0 = O + base + (size_t)(q0 + rowA + lq) * DIM;
    float* d1 = O + base + (size_t)(q0 + rowA + lq + 8) * DIM;
#pragma unroll
    for (int n = 0; n < 8; n++) {
        int col = 8 * n + 2 * lrm;
        float2 w0; w0.x = o_frag[n][0] * i0; w0.y = o_frag[n][1] * i0;
        float2 w1; w1.x = o_frag[n][2] * i1; w1.y = o_frag[n][3] * i1;
        *(float2*)&d0[col] = w0;
        *(float2*)&d1[col] = w1;
    }
}

// ---------------------------------------------------------------------------
extern "C" void kernel_launch(void* const* d_in, const int* in_sizes, int n_in,
                              void* d_out, int out_size) {
    const float* x  = (const float*)d_in[0];
    const float* g1 = (const float*)d_in[1];
    const float* b1 = (const float*)d_in[2];
    const float* Wq = (const float*)d_in[3];
    const float* bq = (const float*)d_in[4];
    const float* Wk = (const float*)d_in[5];
    const float* bk = (const float*)d_in[6];
    const float* Wv = (const float*)d_in[7];
    const float* bv = (const float*)d_in[8];
    const float* Wo = (const float*)d_in[9];
    const float* bo = (const float*)d_in[10];
    float* out = (float*)d_out;

    float *h_p, *q_p, *k_p, *v_p, *a_p;
    cudaGetSymbolAddress((void**)&h_p, g_h);
    cudaGetSymbolAddress((void**)&q_p, g_q);
    cudaGetSymbolAddress((void**)&k_p, g_k);
    cudaGetSymbolAddress((void**)&v_p, g_v);
    cudaGetSymbolAddress((void**)&a_p, g_att);

    const int attn_smem = (QT + 64 + 64 + QT) * FSTR * (int)sizeof(uint32_t); // 104448
    cudaFuncSetAttribute(attn_kernel, cudaFuncAttributeMaxDynamicSharedMemorySize,
                         attn_smem);

    ln_kernel<<<BT, 256>>>(x, g1, b1, h_p);

    dim3 qkv_grid(DIM / 128, BT / 128, 3);
    gemm_qkv<<<qkv_grid, 128>>>(h_p, Wq, bq, q_p, Wk, bk, k_p, Wv, bv, v_p,
                                BT, DIM, DIM);

    attn_kernel<<<dim3(TSEQ / QT, NH, 2), 256, attn_smem>>>(q_p, k_p, v_p, a_p);

    dim3 ggrid(DIM / 128, BT / 128);
    gemm_tf32<<<ggrid, 128>>>(a_p, Wo, bo, out, BT, DIM, DIM);
}

// round 10
// speedup vs baseline: 1.2050x; 1.2050x over previous
#include <cuda_runtime.h>
#include <cstdint>

#define DIM 1024
#define NH 16
#define HD 64
#define TSEQ 2048
#define BT 4096          // B * T
#define GSTR 20          // gemm smem stride (words): conflict-free rows for ldmatrix
#define FSTR 68          // attention smem stride (words)
#define QT 128           // attention query-tile rows

// Scratch (static device arrays; allocation in kernel_launch is forbidden)
__device__ float g_h[BT * DIM];
__device__ float g_q[BT * DIM];
__device__ float g_k[BT * DIM];
__device__ float g_v[BT * DIM];
__device__ float g_att[BT * DIM];

// ---------------------------------------------------------------------------
// LayerNorm: one block per row of x [4096, 1024]
// ---------------------------------------------------------------------------
__global__ void ln_kernel(const float* __restrict__ x,
                          const float* __restrict__ gamma,
                          const float* __restrict__ beta,
                          float* __restrict__ out) {
    int row = blockIdx.x;
    const float* xr = x + (size_t)row * DIM;
    float* orow = out + (size_t)row * DIM;
    int t = threadIdx.x;

    float v[4];
    float sum = 0.f, sq = 0.f;
#pragma unroll
    for (int i = 0; i < 4; i++) {
        float val = xr[t + i * 256];
        v[i] = val;
        sum += val;
        sq += val * val;
    }
#pragma unroll
    for (int o = 16; o > 0; o >>= 1) {
        sum += __shfl_xor_sync(0xffffffffu, sum, o);
        sq  += __shfl_xor_sync(0xffffffffu, sq, o);
    }
    __shared__ float s1[8], s2[8];
    if ((t & 31) == 0) { s1[t >> 5] = sum; s2[t >> 5] = sq; }
    __syncthreads();
    float tot = 0.f, totq = 0.f;
#pragma unroll
    for (int i = 0; i < 8; i++) { tot += s1[i]; totq += s2[i]; }
    float mu   = tot * (1.0f / DIM);
    float var  = totq * (1.0f / DIM) - mu * mu;
    float rstd = rsqrtf(var + 1e-5f);
#pragma unroll
    for (int i = 0; i < 4; i++) {
        int c = t + i * 256;
        orow[c] = (v[i] - mu) * rstd * gamma[c] + beta[c];
    }
}

// ---------------------------------------------------------------------------
// tf32 helpers
// ---------------------------------------------------------------------------
__device__ __forceinline__ uint32_t f2tf(float x) {
    uint32_t y;
    asm("cvt.rna.tf32.f32 %0, %1;" : "=r"(y) : "f"(x));
    return y;
}

__device__ __forceinline__ void mma_tf32(float* c, const uint32_t* a,
                                         const uint32_t* b) {
    asm volatile(
        "mma.sync.aligned.m16n8k8.row.col.f32.tf32.tf32.f32 "
        "{%0,%1,%2,%3}, {%4,%5,%6,%7}, {%8,%9}, {%0,%1,%2,%3};\n"
        : "+f"(c[0]), "+f"(c[1]), "+f"(c[2]), "+f"(c[3])
        : "r"(a[0]), "r"(a[1]), "r"(a[2]), "r"(a[3]), "r"(b[0]), "r"(b[1]));
}

__device__ __forceinline__ void ldsm_x4(uint32_t& r0, uint32_t& r1,
                                        uint32_t& r2, uint32_t& r3,
                                        uint32_t addr) {
    asm volatile(
        "ldmatrix.sync.aligned.m8n8.x4.shared.b16 {%0,%1,%2,%3}, [%4];"
        : "=r"(r0), "=r"(r1), "=r"(r2), "=r"(r3) : "r"(addr));
}

// ---------------------------------------------------------------------------
// tf32 GEMM NT: 128x128 block, 256 threads = 8 warps (2m x 4n), warp tile
// 64x32, BK=16, 2-stage double buffer, ldmatrix fragment loads.
// C[m][n] = sum_k A[m][k]*B[n][k] + bias[n].
// ---------------------------------------------------------------------------
__device__ __forceinline__ void gemm_tf32_body(const float* __restrict__ A,
                                               const float* __restrict__ B,
                                               const float* __restrict__ bias,
                                               float* __restrict__ C,
                                               int M, int N, int K) {
    __shared__ uint32_t As[2][128 * GSTR];
    __shared__ uint32_t Bs[2][128 * GSTR];

    int tid = threadIdx.x;
    int bm = blockIdx.y * 128;
    int bn = blockIdx.x * 128;
    int w = tid >> 5, lane = tid & 31;
    int wm = (w & 1) * 64;        // warp m offset
    int wn = (w >> 1) * 32;       // warp n offset
    int lq = lane >> 2;
    int lrm = lane & 3;
    int lr = tid >> 2;            // load row 0..63
    int lc = (tid & 3) << 2;      // load k offset 0,4,8,12

    const float* Ap = A + (size_t)(bm + lr) * K + lc;
    const float* Bp = B + (size_t)(bn + lr) * K + lc;

    // ldmatrix lane addressing (validated in R8):
    // A tiles: g&1 -> +8 rows, g>>1 -> +4 k   (af[0..3] layout of m16n8k8 A)
    // B tiles: g>>1 -> +8 n-rows, g&1 -> +4 k (r0,r1 = tile n0 k/k+4; r2,r3 = n0+8)
    int g = lane >> 3;
    int lr8 = lane & 7;
    uint32_t aBase = (uint32_t)__cvta_generic_to_shared(&As[0][0]);
    uint32_t bBase = (uint32_t)__cvta_generic_to_shared(&Bs[0][0]);
    const uint32_t stageBytes = 128 * GSTR * 4;
    uint32_t aOff = ((uint32_t)(wm + (g & 1) * 8 + lr8) * GSTR + (g >> 1) * 4) * 4;
    uint32_t bOff = ((uint32_t)(wn + (g >> 1) * 8 + lr8) * GSTR + (g & 1) * 4) * 4;

    float acc[4][4][4];
#pragma unroll
    for (int mi = 0; mi < 4; mi++)
#pragma unroll
        for (int ni = 0; ni < 4; ni++)
#pragma unroll
            for (int r = 0; r < 4; r++) acc[mi][ni][r] = 0.f;

    // Prologue: stage 0
    {
        float4 a0 = *(const float4*)(Ap);
        float4 a1 = *(const float4*)(Ap + (size_t)64 * K);
        float4 b0 = *(const float4*)(Bp);
        float4 b1 = *(const float4*)(Bp + (size_t)64 * K);
        uint4 u;
        u.x = f2tf(a0.x); u.y = f2tf(a0.y); u.z = f2tf(a0.z); u.w = f2tf(a0.w);
        *(uint4*)&As[0][lr * GSTR + lc] = u;
        u.x = f2tf(a1.x); u.y = f2tf(a1.y); u.z = f2tf(a1.z); u.w = f2tf(a1.w);
        *(uint4*)&As[0][(lr + 64) * GSTR + lc] = u;
        u.x = f2tf(b0.x); u.y = f2tf(b0.y); u.z = f2tf(b0.z); u.w = f2tf(b0.w);
        *(uint4*)&Bs[0][lr * GSTR + lc] = u;
        u.x = f2tf(b1.x); u.y = f2tf(b1.y); u.z = f2tf(b1.z); u.w = f2tf(b1.w);
        *(uint4*)&Bs[0][(lr + 64) * GSTR + lc] = u;
    }
    __syncthreads();

    int stage = 0;
    for (int k0 = 0; k0 < K; k0 += 16) {
        int nxt = stage ^ 1;
        bool has_next = (k0 + 16) < K;

        float4 a0, a1, b0, b1;
        if (has_next) {
            a0 = *(const float4*)(Ap + k0 + 16);
            a1 = *(const float4*)(Ap + (size_t)64 * K + k0 + 16);
            b0 = *(const float4*)(Bp + k0 + 16);
            b1 = *(const float4*)(Bp + (size_t)64 * K + k0 + 16);
        }

        uint32_t aS = aBase + stage * stageBytes + aOff;
        uint32_t bS = bBase + stage * stageBytes + bOff;
#pragma unroll
        for (int ks = 0; ks < 16; ks += 8) {
            uint32_t af[4][4];
#pragma unroll
            for (int mi = 0; mi < 4; mi++)
                ldsm_x4(af[mi][0], af[mi][1], af[mi][2], af[mi][3],
                        aS + (uint32_t)(mi * 16 * GSTR + ks) * 4);
            uint32_t bf[4][2];
#pragma unroll
            for (int np = 0; np < 2; np++) {
                uint32_t r0, r1, r2, r3;
                ldsm_x4(r0, r1, r2, r3,
                        bS + (uint32_t)(np * 16 * GSTR + ks) * 4);
                bf[2 * np][0] = r0; bf[2 * np][1] = r1;
                bf[2 * np + 1][0] = r2; bf[2 * np + 1][1] = r3;
            }
#pragma unroll
            for (int mi = 0; mi < 4; mi++)
#pragma unroll
                for (int ni = 0; ni < 4; ni++)
                    mma_tf32(acc[mi][ni], af[mi], bf[ni]);
        }

        if (has_next) {
            uint4 u;
            u.x = f2tf(a0.x); u.y = f2tf(a0.y); u.z = f2tf(a0.z); u.w = f2tf(a0.w);
            *(uint4*)&As[nxt][lr * GSTR + lc] = u;
            u.x = f2tf(a1.x); u.y = f2tf(a1.y); u.z = f2tf(a1.z); u.w = f2tf(a1.w);
            *(uint4*)&As[nxt][(lr + 64) * GSTR + lc] = u;
            u.x = f2tf(b0.x); u.y = f2tf(b0.y); u.z = f2tf(b0.z); u.w = f2tf(b0.w);
            *(uint4*)&Bs[nxt][lr * GSTR + lc] = u;
            u.x = f2tf(b1.x); u.y = f2tf(b1.y); u.z = f2tf(b1.z); u.w = f2tf(b1.w);
            *(uint4*)&Bs[nxt][(lr + 64) * GSTR + lc] = u;
            __syncthreads();
        }
        stage = nxt;
    }

#pragma unroll
    for (int mi = 0; mi < 4; mi++) {
#pragma unroll
        for (int ni = 0; ni < 4; ni++) {
            int row0 = bm + wm + mi * 16 + lq;
            int col  = bn + wn + ni * 8 + lrm * 2;
            float2 bb = *(const float2*)&bias[col];
            float2 o0, o1;
            o0.x = acc[mi][ni][0] + bb.x;
            o0.y = acc[mi][ni][1] + bb.y;
            o1.x = acc[mi][ni][2] + bb.x;
            o1.y = acc[mi][ni][3] + bb.y;
            *(float2*)&C[(size_t)row0 * N + col] = o0;
            *(float2*)&C[(size_t)(row0 + 8) * N + col] = o1;
        }
    }
}

__global__ __launch_bounds__(256) void gemm_tf32(const float* __restrict__ A,
                                                 const float* __restrict__ B,
                                                 const float* __restrict__ bias,
                                                 float* __restrict__ C,
                                                 int M, int N, int K) {
    gemm_tf32_body(A, B, bias, C, M, N, K);
}

__global__ __launch_bounds__(256) void gemm_qkv(const float* __restrict__ A,
                                                const float* __restrict__ Wq,
                                                const float* __restrict__ bq,
                                                float* __restrict__ Oq,
                                                const float* __restrict__ Wk,
                                                const float* __restrict__ bk,
                                                float* __restrict__ Ok,
                                                const float* __restrict__ Wv,
                                                const float* __restrict__ bv,
                                                float* __restrict__ Ov,
                                                int M, int N, int K) {
    int z = blockIdx.z;
    const float* W = (z == 0) ? Wq : (z == 1) ? Wk : Wv;
    const float* b = (z == 0) ? bq : (z == 1) ? bk : bv;
    float* O       = (z == 0) ? Oq : (z == 1) ? Ok : Ov;
    gemm_tf32_body(A, W, b, O, M, N, K);
}

// ---------------------------------------------------------------------------
// Tensor-core causal flash attention, 128-row Q tile (frozen from R7).
// ---------------------------------------------------------------------------
__global__ __launch_bounds__(256) void attn_kernel(const float* __restrict__ Q,
                                                   const float* __restrict__ K,
                                                   const float* __restrict__ V,
                                                   float* __restrict__ O) {
    extern __shared__ uint32_t sm[];
    uint32_t* sQ  = sm;                   // QT*FSTR
    uint32_t* sK  = sQ + QT * FSTR;       // 64*FSTR
    uint32_t* sVt = sK + 64 * FSTR;       // 64*FSTR  (sVt[d*FSTR + key])
    uint32_t* sP  = sVt + 64 * FSTR;      // QT*FSTR

    int tid = threadIdx.x;
    int w = tid >> 5, lane = tid & 31;
    int lq = lane >> 2, lrm = lane & 3;
    int rowA = w * 16;
    int qblk = blockIdx.x;
    int h = blockIdx.y;
    int b = blockIdx.z;
    int q0 = qblk * QT;
    size_t base = ((size_t)b * TSEQ) * DIM + h * HD;

    int qlr = tid >> 1;
    int qlc = (tid & 1) * 32;
    int klr = tid & 63;
    int klc = (tid >> 6) * 16;

    {
        const float* src = Q + base + (size_t)(q0 + qlr) * DIM + qlc;
        uint32_t* dst = sQ + qlr * FSTR + qlc;
#pragma unroll
        for (int i = 0; i < 8; i++) {
            float4 t4 = *(const float4*)(src + 4 * i);
            dst[4 * i + 0] = f2tf(t4.x); dst[4 * i + 1] = f2tf(t4.y);
            dst[4 * i + 2] = f2tf(t4.z); dst[4 * i + 3] = f2tf(t4.w);
        }
    }

    float o_frag[8][4];
#pragma unroll
    for (int n = 0; n < 8; n++)
#pragma unroll
        for (int r = 0; r < 4; r++) o_frag[n][r] = 0.f;
    float m0 = -1e30f, m1 = -1e30f, l0 = 0.f, l1 = 0.f;

    int kb_max = 2 * qblk + 1;
    for (int kb = 0; kb <= kb_max; kb++) {
        __syncthreads();
        {
            const float* ksrc = K + base + (size_t)(kb * 64 + klr) * DIM + klc;
            const float* vsrc = V + base + (size_t)(kb * 64 + klr) * DIM + klc;
            uint32_t* kd = sK + klr * FSTR + klc;
#pragma unroll
            for (int i = 0; i < 4; i++) {
                float4 kt = *(const float4*)(ksrc + 4 * i);
                uint4 u;
                u.x = f2tf(kt.x); u.y = f2tf(kt.y);
                u.z = f2tf(kt.z); u.w = f2tf(kt.w);
                *(uint4*)&kd[4 * i] = u;
                float4 vt = *(const float4*)(vsrc + 4 * i);
                sVt[(klc + 4 * i + 0) * FSTR + klr] = f2tf(vt.x);
                sVt[(klc + 4 * i + 1) * FSTR + klr] = f2tf(vt.y);
                sVt[(klc + 4 * i + 2) * FSTR + klr] = f2tf(vt.z);
                sVt[(klc + 4 * i + 3) * FSTR + klr] = f2tf(vt.w);
            }
        }
        __syncthreads();

        if (kb * 64 > q0 + rowA + 15) continue;   // fully masked, warp-uniform

        float s_frag[8][4];
#pragma unroll
        for (int n = 0; n < 8; n++)
#pragma unroll
            for (int r = 0; r < 4; r++) s_frag[n][r] = 0.f;

#pragma unroll
        for (int ks = 0; ks < 64; ks += 8) {
            uint32_t af[4];
            af[0] = sQ[(rowA + lq) * FSTR + ks + lrm];
            af[1] = sQ[(rowA + lq + 8) * FSTR + ks + lrm];
            af[2] = sQ[(rowA + lq) * FSTR + ks + lrm + 4];
            af[3] = sQ[(rowA + lq + 8) * FSTR + ks + lrm + 4];
#pragma unroll
            for (int n = 0; n < 8; n++) {
                uint32_t bf[2];
                bf[0] = sK[(8 * n + lq) * FSTR + ks + lrm];
                bf[1] = sK[(8 * n + lq) * FSTR + ks + lrm + 4];
                mma_tf32(s_frag[n], af, bf);
            }
        }
#pragma unroll
        for (int n = 0; n < 8; n++)
#pragma unroll
            for (int r = 0; r < 4; r++) s_frag[n][r] *= 0.125f;

        if (kb * 64 + 63 > q0 + rowA) {
            int r0 = q0 + rowA + lq, r1 = q0 + rowA + lq + 8;
            int cbase = kb * 64;
#pragma unroll
            for (int n = 0; n < 8; n++) {
                int c = cbase + 8 * n + 2 * lrm;
                if (c > r0)     s_frag[n][0] = -1e30f;
                if (c + 1 > r0) s_frag[n][1] = -1e30f;
                if (c > r1)     s_frag[n][2] = -1e30f;
                if (c + 1 > r1) s_frag[n][3] = -1e30f;
            }
        }

        {
            float mloc0 = -1e30f, mloc1 = -1e30f;
#pragma unroll
            for (int n = 0; n < 8; n++) {
                mloc0 = fmaxf(mloc0, fmaxf(s_frag[n][0], s_frag[n][1]));
                mloc1 = fmaxf(mloc1, fmaxf(s_frag[n][2], s_frag[n][3]));
            }
            mloc0 = fmaxf(mloc0, __shfl_xor_sync(0xffffffffu, mloc0, 1));
            mloc0 = fmaxf(mloc0, __shfl_xor_sync(0xffffffffu, mloc0, 2));
            mloc1 = fmaxf(mloc1, __shfl_xor_sync(0xffffffffu, mloc1, 1));
            mloc1 = fmaxf(mloc1, __shfl_xor_sync(0xffffffffu, mloc1, 2));
            float mn0 = fmaxf(m0, mloc0), mn1 = fmaxf(m1, mloc1);
            float c0 = __expf(m0 - mn0), c1 = __expf(m1 - mn1);
            float ps0 = 0.f, ps1 = 0.f;
#pragma unroll
            for (int n = 0; n < 8; n++) {
                float p0 = __expf(s_frag[n][0] - mn0);
                float p1 = __expf(s_frag[n][1] - mn0);
                float p2 = __expf(s_frag[n][2] - mn1);
                float p3 = __expf(s_frag[n][3] - mn1);
                s_frag[n][0] = p0; s_frag[n][1] = p1;
                s_frag[n][2] = p2; s_frag[n][3] = p3;
                ps0 += p0 + p1; ps1 += p2 + p3;
            }
            ps0 += __shfl_xor_sync(0xffffffffu, ps0, 1);
            ps0 += __shfl_xor_sync(0xffffffffu, ps0, 2);
            ps1 += __shfl_xor_sync(0xffffffffu, ps1, 1);
            ps1 += __shfl_xor_sync(0xffffffffu, ps1, 2);
            l0 = l0 * c0 + ps0; m0 = mn0;
            l1 = l1 * c1 + ps1; m1 = mn1;
#pragma unroll
            for (int n = 0; n < 8; n++) {
                o_frag[n][0] *= c0; o_frag[n][1] *= c0;
                o_frag[n][2] *= c1; o_frag[n][3] *= c1;
            }
        }

#pragma unroll
        for (int n = 0; n < 8; n++) {
            uint2 p01; p01.x = f2tf(s_frag[n][0]); p01.y = f2tf(s_frag[n][1]);
            *(uint2*)&sP[(rowA + lq) * FSTR + 8 * n + 2 * lrm] = p01;
            uint2 p23; p23.x = f2tf(s_frag[n][2]); p23.y = f2tf(s_frag[n][3]);
            *(uint2*)&sP[(rowA + lq + 8) * FSTR + 8 * n + 2 * lrm] = p23;
        }
        __syncwarp();

#pragma unroll
        for (int ks = 0; ks < 64; ks += 8) {
            uint32_t af[4];
            af[0] = sP[(rowA + lq) * FSTR + ks + lrm];
            af[1] = sP[(rowA + lq + 8) * FSTR + ks + lrm];
            af[2] = sP[(rowA + lq) * FSTR + ks + lrm + 4];
            af[3] = sP[(rowA + lq + 8) * FSTR + ks + lrm + 4];
#pragma unroll
            for (int n = 0; n < 8; n++) {
                uint32_t bf[2];
                bf[0] = sVt[(8 * n + lq) * FSTR + ks + lrm];
                bf[1] = sVt[(8 * n + lq) * FSTR + ks + lrm + 4];
                mma_tf32(o_frag[n], af, bf);
            }
        }
    }

    float i0 = 1.0f / l0, i1 = 1.0f / l1;
    float* d0 = O + base + (size_t)(q0 + rowA + lq) * DIM;
    float* d1 = O + base + (size_t)(q0 + rowA + lq + 8) * DIM;
#pragma unroll
    for (int n = 0; n < 8; n++) {
        int col = 8 * n + 2 * lrm;
        float2 w0; w0.x = o_frag[n][0] * i0; w0.y = o_frag[n][1] * i0;
        float2 w1; w1.x = o_frag[n][2] * i1; w1.y = o_frag[n][3] * i1;
        *(float2*)&d0[col] = w0;
        *(float2*)&d1[col] = w1;
    }
}

// ---------------------------------------------------------------------------
extern "C" void kernel_launch(void* const* d_in, const int* in_sizes, int n_in,
                              void* d_out, int out_size) {
    const float* x  = (const float*)d_in[0];
    const float* g1 = (const float*)d_in[1];
    const float* b1 = (const float*)d_in[2];
    const float* Wq = (const float*)d_in[3];
    const float* bq = (const float*)d_in[4];
    const float* Wk = (const float*)d_in[5];
    const float* bk = (const float*)d_in[6];
    const float* Wv = (const float*)d_in[7];
    const float* bv = (const float*)d_in[8];
    const float* Wo = (const float*)d_in[9];
    const float* bo = (const float*)d_in[10];
    float* out = (float*)d_out;

    float *h_p, *q_p, *k_p, *v_p, *a_p;
    cudaGetSymbolAddress((void**)&h_p, g_h);
    cudaGetSymbolAddress((void**)&q_p, g_q);
    cudaGetSymbolAddress((void**)&k_p, g_k);
    cudaGetSymbolAddress((void**)&v_p, g_v);
    cudaGetSymbolAddress((void**)&a_p, g_att);

    const int attn_smem = (QT + 64 + 64 + QT) * FSTR * (int)sizeof(uint32_t); // 104448
    cudaFuncSetAttribute(attn_kernel, cudaFuncAttributeMaxDynamicSharedMemorySize,
                         attn_smem);

    ln_kernel<<<BT, 256>>>(x, g1, b1, h_p);

    dim3 qkv_grid(DIM / 128, BT / 128, 3);
    gemm_qkv<<<qkv_grid, 256>>>(h_p, Wq, bq, q_p, Wk, bk, k_p, Wv, bv, v_p,
                                BT, DIM, DIM);

    attn_kernel<<<dim3(TSEQ / QT, NH, 2), 256, attn_smem>>>(q_p, k_p, v_p, a_p);

    dim3 ggrid(DIM / 128, BT / 128);
    gemm_tf32<<<ggrid, 256>>>(a_p, Wo, bo, out, BT, DIM, DIM);
}

// round 11
// speedup vs baseline: 1.2420x; 1.0307x over previous
#include <cuda_runtime.h>
#include <cstdint>

#define DIM 1024
#define NH 16
#define HD 64
#define TSEQ 2048
#define BT 4096          // B * T
#define GSTR 20          // gemm smem stride (words): conflict-free rows for ldmatrix
#define FSTR 68          // attention smem stride (words): r*68 mod 32 spans all banks
#define QT 128           // attention query-tile rows

// Scratch (static device arrays; allocation in kernel_launch is forbidden)
__device__ float g_h[BT * DIM];
__device__ float g_q[BT * DIM];
__device__ float g_k[BT * DIM];
__device__ float g_v[BT * DIM];
__device__ float g_att[BT * DIM];

// ---------------------------------------------------------------------------
// LayerNorm: one block per row of x [4096, 1024]
// ---------------------------------------------------------------------------
__global__ void ln_kernel(const float* __restrict__ x,
                          const float* __restrict__ gamma,
                          const float* __restrict__ beta,
                          float* __restrict__ out) {
    int row = blockIdx.x;
    const float* xr = x + (size_t)row * DIM;
    float* orow = out + (size_t)row * DIM;
    int t = threadIdx.x;

    float v[4];
    float sum = 0.f, sq = 0.f;
#pragma unroll
    for (int i = 0; i < 4; i++) {
        float val = xr[t + i * 256];
        v[i] = val;
        sum += val;
        sq += val * val;
    }
#pragma unroll
    for (int o = 16; o > 0; o >>= 1) {
        sum += __shfl_xor_sync(0xffffffffu, sum, o);
        sq  += __shfl_xor_sync(0xffffffffu, sq, o);
    }
    __shared__ float s1[8], s2[8];
    if ((t & 31) == 0) { s1[t >> 5] = sum; s2[t >> 5] = sq; }
    __syncthreads();
    float tot = 0.f, totq = 0.f;
#pragma unroll
    for (int i = 0; i < 8; i++) { tot += s1[i]; totq += s2[i]; }
    float mu   = tot * (1.0f / DIM);
    float var  = totq * (1.0f / DIM) - mu * mu;
    float rstd = rsqrtf(var + 1e-5f);
#pragma unroll
    for (int i = 0; i < 4; i++) {
        int c = t + i * 256;
        orow[c] = (v[i] - mu) * rstd * gamma[c] + beta[c];
    }
}

// ---------------------------------------------------------------------------
// tf32 helpers
// ---------------------------------------------------------------------------
__device__ __forceinline__ uint32_t f2tf(float x) {
    uint32_t y;
    asm("cvt.rna.tf32.f32 %0, %1;" : "=r"(y) : "f"(x));
    return y;
}

__device__ __forceinline__ void mma_tf32(float* c, const uint32_t* a,
                                         const uint32_t* b) {
    asm volatile(
        "mma.sync.aligned.m16n8k8.row.col.f32.tf32.tf32.f32 "
        "{%0,%1,%2,%3}, {%4,%5,%6,%7}, {%8,%9}, {%0,%1,%2,%3};\n"
        : "+f"(c[0]), "+f"(c[1]), "+f"(c[2]), "+f"(c[3])
        : "r"(a[0]), "r"(a[1]), "r"(a[2]), "r"(a[3]), "r"(b[0]), "r"(b[1]));
}

__device__ __forceinline__ void ldsm_x4(uint32_t& r0, uint32_t& r1,
                                        uint32_t& r2, uint32_t& r3,
                                        uint32_t addr) {
    asm volatile(
        "ldmatrix.sync.aligned.m8n8.x4.shared.b16 {%0,%1,%2,%3}, [%4];"
        : "=r"(r0), "=r"(r1), "=r"(r2), "=r"(r3) : "r"(addr));
}

// ---------------------------------------------------------------------------
// tf32 GEMM NT: 128x128 block, 256 threads = 8 warps (2m x 4n), warp tile
// 64x32, BK=16, 2-stage double buffer, ldmatrix fragment loads. (frozen R9)
// ---------------------------------------------------------------------------
__device__ __forceinline__ void gemm_tf32_body(const float* __restrict__ A,
                                               const float* __restrict__ B,
                                               const float* __restrict__ bias,
                                               float* __restrict__ C,
                                               int M, int N, int K) {
    __shared__ uint32_t As[2][128 * GSTR];
    __shared__ uint32_t Bs[2][128 * GSTR];

    int tid = threadIdx.x;
    int bm = blockIdx.y * 128;
    int bn = blockIdx.x * 128;
    int w = tid >> 5, lane = tid & 31;
    int wm = (w & 1) * 64;
    int wn = (w >> 1) * 32;
    int lq = lane >> 2;
    int lrm = lane & 3;
    int lr = tid >> 2;
    int lc = (tid & 3) << 2;

    const float* Ap = A + (size_t)(bm + lr) * K + lc;
    const float* Bp = B + (size_t)(bn + lr) * K + lc;

    int g = lane >> 3;
    int lr8 = lane & 7;
    uint32_t aBase = (uint32_t)__cvta_generic_to_shared(&As[0][0]);
    uint32_t bBase = (uint32_t)__cvta_generic_to_shared(&Bs[0][0]);
    const uint32_t stageBytes = 128 * GSTR * 4;
    uint32_t aOff = ((uint32_t)(wm + (g & 1) * 8 + lr8) * GSTR + (g >> 1) * 4) * 4;
    uint32_t bOff = ((uint32_t)(wn + (g >> 1) * 8 + lr8) * GSTR + (g & 1) * 4) * 4;

    float acc[4][4][4];
#pragma unroll
    for (int mi = 0; mi < 4; mi++)
#pragma unroll
        for (int ni = 0; ni < 4; ni++)
#pragma unroll
            for (int r = 0; r < 4; r++) acc[mi][ni][r] = 0.f;

    {
        float4 a0 = *(const float4*)(Ap);
        float4 a1 = *(const float4*)(Ap + (size_t)64 * K);
        float4 b0 = *(const float4*)(Bp);
        float4 b1 = *(const float4*)(Bp + (size_t)64 * K);
        uint4 u;
        u.x = f2tf(a0.x); u.y = f2tf(a0.y); u.z = f2tf(a0.z); u.w = f2tf(a0.w);
        *(uint4*)&As[0][lr * GSTR + lc] = u;
        u.x = f2tf(a1.x); u.y = f2tf(a1.y); u.z = f2tf(a1.z); u.w = f2tf(a1.w);
        *(uint4*)&As[0][(lr + 64) * GSTR + lc] = u;
        u.x = f2tf(b0.x); u.y = f2tf(b0.y); u.z = f2tf(b0.z); u.w = f2tf(b0.w);
        *(uint4*)&Bs[0][lr * GSTR + lc] = u;
        u.x = f2tf(b1.x); u.y = f2tf(b1.y); u.z = f2tf(b1.z); u.w = f2tf(b1.w);
        *(uint4*)&Bs[0][(lr + 64) * GSTR + lc] = u;
    }
    __syncthreads();

    int stage = 0;
    for (int k0 = 0; k0 < K; k0 += 16) {
        int nxt = stage ^ 1;
        bool has_next = (k0 + 16) < K;

        float4 a0, a1, b0, b1;
        if (has_next) {
            a0 = *(const float4*)(Ap + k0 + 16);
            a1 = *(const float4*)(Ap + (size_t)64 * K + k0 + 16);
            b0 = *(const float4*)(Bp + k0 + 16);
            b1 = *(const float4*)(Bp + (size_t)64 * K + k0 + 16);
        }

        uint32_t aS = aBase + stage * stageBytes + aOff;
        uint32_t bS = bBase + stage * stageBytes + bOff;
#pragma unroll
        for (int ks = 0; ks < 16; ks += 8) {
            uint32_t af[4][4];
#pragma unroll
            for (int mi = 0; mi < 4; mi++)
                ldsm_x4(af[mi][0], af[mi][1], af[mi][2], af[mi][3],
                        aS + (uint32_t)(mi * 16 * GSTR + ks) * 4);
            uint32_t bf[4][2];
#pragma unroll
            for (int np = 0; np < 2; np++) {
                uint32_t r0, r1, r2, r3;
                ldsm_x4(r0, r1, r2, r3,
                        bS + (uint32_t)(np * 16 * GSTR + ks) * 4);
                bf[2 * np][0] = r0; bf[2 * np][1] = r1;
                bf[2 * np + 1][0] = r2; bf[2 * np + 1][1] = r3;
            }
#pragma unroll
            for (int mi = 0; mi < 4; mi++)
#pragma unroll
                for (int ni = 0; ni < 4; ni++)
                    mma_tf32(acc[mi][ni], af[mi], bf[ni]);
        }

        if (has_next) {
            uint4 u;
            u.x = f2tf(a0.x); u.y = f2tf(a0.y); u.z = f2tf(a0.z); u.w = f2tf(a0.w);
            *(uint4*)&As[nxt][lr * GSTR + lc] = u;
            u.x = f2tf(a1.x); u.y = f2tf(a1.y); u.z = f2tf(a1.z); u.w = f2tf(a1.w);
            *(uint4*)&As[nxt][(lr + 64) * GSTR + lc] = u;
            u.x = f2tf(b0.x); u.y = f2tf(b0.y); u.z = f2tf(b0.z); u.w = f2tf(b0.w);
            *(uint4*)&Bs[nxt][lr * GSTR + lc] = u;
            u.x = f2tf(b1.x); u.y = f2tf(b1.y); u.z = f2tf(b1.z); u.w = f2tf(b1.w);
            *(uint4*)&Bs[nxt][(lr + 64) * GSTR + lc] = u;
            __syncthreads();
        }
        stage = nxt;
    }

#pragma unroll
    for (int mi = 0; mi < 4; mi++) {
#pragma unroll
        for (int ni = 0; ni < 4; ni++) {
            int row0 = bm + wm + mi * 16 + lq;
            int col  = bn + wn + ni * 8 + lrm * 2;
            float2 bb = *(const float2*)&bias[col];
            float2 o0, o1;
            o0.x = acc[mi][ni][0] + bb.x;
            o0.y = acc[mi][ni][1] + bb.y;
            o1.x = acc[mi][ni][2] + bb.x;
            o1.y = acc[mi][ni][3] + bb.y;
            *(float2*)&C[(size_t)row0 * N + col] = o0;
            *(float2*)&C[(size_t)(row0 + 8) * N + col] = o1;
        }
    }
}

__global__ __launch_bounds__(256) void gemm_tf32(const float* __restrict__ A,
                                                 const float* __restrict__ B,
                                                 const float* __restrict__ bias,
                                                 float* __restrict__ C,
                                                 int M, int N, int K) {
    gemm_tf32_body(A, B, bias, C, M, N, K);
}

__global__ __launch_bounds__(256) void gemm_qkv(const float* __restrict__ A,
                                                const float* __restrict__ Wq,
                                                const float* __restrict__ bq,
                                                float* __restrict__ Oq,
                                                const float* __restrict__ Wk,
                                                const float* __restrict__ bk,
                                                float* __restrict__ Ok,
                                                const float* __restrict__ Wv,
                                                const float* __restrict__ bv,
                                                float* __restrict__ Ov,
                                                int M, int N, int K) {
    int z = blockIdx.z;
    const float* W = (z == 0) ? Wq : (z == 1) ? Wk : Wv;
    const float* b = (z == 0) ? bq : (z == 1) ? bk : bv;
    float* O       = (z == 0) ? Oq : (z == 1) ? Ok : Ov;
    gemm_tf32_body(A, W, b, O, M, N, K);
}

// ---------------------------------------------------------------------------
// Tensor-core causal flash attention, 128-row Q tile, ldmatrix fragment loads.
// Grid: (T/128, NH, B). Block: 256 threads = 8 warps; warp w owns q rows
// [16w, 16w+16). K tiles of 64. S and PV via mma.sync.m16n8k8 (tf32).
// ---------------------------------------------------------------------------
__global__ __launch_bounds__(256) void attn_kernel(const float* __restrict__ Q,
                                                   const float* __restrict__ K,
                                                   const float* __restrict__ V,
                                                   float* __restrict__ O) {
    extern __shared__ uint32_t sm[];
    uint32_t* sQ  = sm;                   // QT*FSTR
    uint32_t* sK  = sQ + QT * FSTR;       // 64*FSTR
    uint32_t* sVt = sK + 64 * FSTR;       // 64*FSTR  (sVt[d*FSTR + key])
    uint32_t* sP  = sVt + 64 * FSTR;      // QT*FSTR

    int tid = threadIdx.x;
    int w = tid >> 5, lane = tid & 31;
    int lq = lane >> 2, lrm = lane & 3;
    int rowA = w * 16;
    int qblk = blockIdx.x;
    int h = blockIdx.y;
    int b = blockIdx.z;
    int q0 = qblk * QT;
    size_t base = ((size_t)b * TSEQ) * DIM + h * HD;

    int qlr = tid >> 1;
    int qlc = (tid & 1) * 32;
    int klr = tid & 63;
    int klc = (tid >> 6) * 16;

    // ldmatrix lane addressing (same mapping as GEMM, validated):
    // A-operand tiles: g&1 -> +8 rows, g>>1 -> +4 k
    // B-operand tiles: g>>1 -> +8 rows, g&1 -> +4 k
    int g = lane >> 3;
    int lr8 = lane & 7;
    uint32_t smBase = (uint32_t)__cvta_generic_to_shared(sm);
    uint32_t aRowOff = ((uint32_t)((g & 1) * 8 + lr8) * FSTR + (g >> 1) * 4) * 4;
    uint32_t bRowOff = ((uint32_t)((g >> 1) * 8 + lr8) * FSTR + (g & 1) * 4) * 4;
    uint32_t sQa  = smBase + (uint32_t)(rowA * FSTR) * 4 + aRowOff;
    uint32_t sKa  = smBase + (uint32_t)((QT) * FSTR) * 4 + bRowOff;
    uint32_t sVta = smBase + (uint32_t)((QT + 64) * FSTR) * 4 + bRowOff;
    uint32_t sPa  = smBase + (uint32_t)((QT + 128 + rowA) * FSTR) * 4 + aRowOff;

    {
        const float* src = Q + base + (size_t)(q0 + qlr) * DIM + qlc;
        uint32_t* dst = sQ + qlr * FSTR + qlc;
#pragma unroll
        for (int i = 0; i < 8; i++) {
            float4 t4 = *(const float4*)(src + 4 * i);
            dst[4 * i + 0] = f2tf(t4.x); dst[4 * i + 1] = f2tf(t4.y);
            dst[4 * i + 2] = f2tf(t4.z); dst[4 * i + 3] = f2tf(t4.w);
        }
    }

    float o_frag[8][4];
#pragma unroll
    for (int n = 0; n < 8; n++)
#pragma unroll
        for (int r = 0; r < 4; r++) o_frag[n][r] = 0.f;
    float m0 = -1e30f, m1 = -1e30f, l0 = 0.f, l1 = 0.f;

    int kb_max = 2 * qblk + 1;
    for (int kb = 0; kb <= kb_max; kb++) {
        __syncthreads();
        {
            const float* ksrc = K + base + (size_t)(kb * 64 + klr) * DIM + klc;
            const float* vsrc = V + base + (size_t)(kb * 64 + klr) * DIM + klc;
            uint32_t* kd = sK + klr * FSTR + klc;
#pragma unroll
            for (int i = 0; i < 4; i++) {
                float4 kt = *(const float4*)(ksrc + 4 * i);
                uint4 u;
                u.x = f2tf(kt.x); u.y = f2tf(kt.y);
                u.z = f2tf(kt.z); u.w = f2tf(kt.w);
                *(uint4*)&kd[4 * i] = u;
                float4 vt = *(const float4*)(vsrc + 4 * i);
                sVt[(klc + 4 * i + 0) * FSTR + klr] = f2tf(vt.x);
                sVt[(klc + 4 * i + 1) * FSTR + klr] = f2tf(vt.y);
                sVt[(klc + 4 * i + 2) * FSTR + klr] = f2tf(vt.z);
                sVt[(klc + 4 * i + 3) * FSTR + klr] = f2tf(vt.w);
            }
        }
        __syncthreads();

        if (kb * 64 > q0 + rowA + 15) continue;   // fully masked, warp-uniform

        // ---- S = Q K^T via mma + ldmatrix ----
        float s_frag[8][4];
#pragma unroll
        for (int n = 0; n < 8; n++)
#pragma unroll
            for (int r = 0; r < 4; r++) s_frag[n][r] = 0.f;

#pragma unroll
        for (int ks = 0; ks < 64; ks += 8) {
            uint32_t af[4];
            ldsm_x4(af[0], af[1], af[2], af[3], sQa + (uint32_t)ks * 4);
            uint32_t bf[8][2];
#pragma unroll
            for (int np = 0; np < 4; np++) {
                uint32_t r0, r1, r2, r3;
                ldsm_x4(r0, r1, r2, r3,
                        sKa + (uint32_t)(np * 16 * FSTR + ks) * 4);
                bf[2 * np][0] = r0; bf[2 * np][1] = r1;
                bf[2 * np + 1][0] = r2; bf[2 * np + 1][1] = r3;
            }
#pragma unroll
            for (int n = 0; n < 8; n++)
                mma_tf32(s_frag[n], af, bf[n]);
        }
#pragma unroll
        for (int n = 0; n < 8; n++)
#pragma unroll
            for (int r = 0; r < 4; r++) s_frag[n][r] *= 0.125f;

        if (kb * 64 + 63 > q0 + rowA) {
            int r0 = q0 + rowA + lq, r1 = q0 + rowA + lq + 8;
            int cbase = kb * 64;
#pragma unroll
            for (int n = 0; n < 8; n++) {
                int c = cbase + 8 * n + 2 * lrm;
                if (c > r0)     s_frag[n][0] = -1e30f;
                if (c + 1 > r0) s_frag[n][1] = -1e30f;
                if (c > r1)     s_frag[n][2] = -1e30f;
                if (c + 1 > r1) s_frag[n][3] = -1e30f;
            }
        }

        // ---- online softmax on fragments ----
        {
            float mloc0 = -1e30f, mloc1 = -1e30f;
#pragma unroll
            for (int n = 0; n < 8; n++) {
                mloc0 = fmaxf(mloc0, fmaxf(s_frag[n][0], s_frag[n][1]));
                mloc1 = fmaxf(mloc1, fmaxf(s_frag[n][2], s_frag[n][3]));
            }
            mloc0 = fmaxf(mloc0, __shfl_xor_sync(0xffffffffu, mloc0, 1));
            mloc0 = fmaxf(mloc0, __shfl_xor_sync(0xffffffffu, mloc0, 2));
            mloc1 = fmaxf(mloc1, __shfl_xor_sync(0xffffffffu, mloc1, 1));
            mloc1 = fmaxf(mloc1, __shfl_xor_sync(0xffffffffu, mloc1, 2));
            float mn0 = fmaxf(m0, mloc0), mn1 = fmaxf(m1, mloc1);
            float c0 = __expf(m0 - mn0), c1 = __expf(m1 - mn1);
            float ps0 = 0.f, ps1 = 0.f;
#pragma unroll
            for (int n = 0; n < 8; n++) {
                float p0 = __expf(s_frag[n][0] - mn0);
                float p1 = __expf(s_frag[n][1] - mn0);
                float p2 = __expf(s_frag[n][2] - mn1);
                float p3 = __expf(s_frag[n][3] - mn1);
                s_frag[n][0] = p0; s_frag[n][1] = p1;
                s_frag[n][2] = p2; s_frag[n][3] = p3;
                ps0 += p0 + p1; ps1 += p2 + p3;
            }
            ps0 += __shfl_xor_sync(0xffffffffu, ps0, 1);
            ps0 += __shfl_xor_sync(0xffffffffu, ps0, 2);
            ps1 += __shfl_xor_sync(0xffffffffu, ps1, 1);
            ps1 += __shfl_xor_sync(0xffffffffu, ps1, 2);
            l0 = l0 * c0 + ps0; m0 = mn0;
            l1 = l1 * c1 + ps1; m1 = mn1;
#pragma unroll
            for (int n = 0; n < 8; n++) {
                o_frag[n][0] *= c0; o_frag[n][1] *= c0;
                o_frag[n][2] *= c1; o_frag[n][3] *= c1;
            }
        }

        // ---- write P (tf32) to smem; own-warp rows only -> syncwarp ----
#pragma unroll
        for (int n = 0; n < 8; n++) {
            uint2 p01; p01.x = f2tf(s_frag[n][0]); p01.y = f2tf(s_frag[n][1]);
            *(uint2*)&sP[(rowA + lq) * FSTR + 8 * n + 2 * lrm] = p01;
            uint2 p23; p23.x = f2tf(s_frag[n][2]); p23.y = f2tf(s_frag[n][3]);
            *(uint2*)&sP[(rowA + lq + 8) * FSTR + 8 * n + 2 * lrm] = p23;
        }
        __syncwarp();

        // ---- O += P V via mma + ldmatrix (B operand = V^T from sVt) ----
#pragma unroll
        for (int ks = 0; ks < 64; ks += 8) {
            uint32_t af[4];
            ldsm_x4(af[0], af[1], af[2], af[3], sPa + (uint32_t)ks * 4);
            uint32_t bf[8][2];
#pragma unroll
            for (int np = 0; np < 4; np++) {
                uint32_t r0, r1, r2, r3;
                ldsm_x4(r0, r1, r2, r3,
                        sVta + (uint32_t)(np * 16 * FSTR + ks) * 4);
                bf[2 * np][0] = r0; bf[2 * np][1] = r1;
                bf[2 * np + 1][0] = r2; bf[2 * np + 1][1] = r3;
            }
#pragma unroll
            for (int n = 0; n < 8; n++)
                mma_tf32(o_frag[n], af, bf[n]);
        }
    }

    float i0 = 1.0f / l0, i1 = 1.0f / l1;
    float* d0 = O + base + (size_t)(q0 + rowA + lq) * DIM;
    float* d1 = O + base + (size_t)(q0 + rowA + lq + 8) * DIM;
#pragma unroll
    for (int n = 0; n < 8; n++) {
        int col = 8 * n + 2 * lrm;
        float2 w0; w0.x = o_frag[n][0] * i0; w0.y = o_frag[n][1] * i0;
        float2 w1; w1.x = o_frag[n][2] * i1; w1.y = o_frag[n][3] * i1;
        *(float2*)&d0[col] = w0;
        *(float2*)&d1[col] = w1;
    }
}

// ---------------------------------------------------------------------------
extern "C" void kernel_launch(void* const* d_in, const int* in_sizes, int n_in,
                              void* d_out, int out_size) {
    const float* x  = (const float*)d_in[0];
    const float* g1 = (const float*)d_in[1];
    const float* b1 = (const float*)d_in[2];
    const float* Wq = (const float*)d_in[3];
    const float* bq = (const float*)d_in[4];
    const float* Wk = (const float*)d_in[5];
    const float* bk = (const float*)d_in[6];
    const float* Wv = (const float*)d_in[7];
    const float* bv = (const float*)d_in[8];
    const float* Wo = (const float*)d_in[9];
    const float* bo = (const float*)d_in[10];
    float* out = (float*)d_out;

    float *h_p, *q_p, *k_p, *v_p, *a_p;
    cudaGetSymbolAddress((void**)&h_p, g_h);
    cudaGetSymbolAddress((void**)&q_p, g_q);
    cudaGetSymbolAddress((void**)&k_p, g_k);
    cudaGetSymbolAddress((void**)&v_p, g_v);
    cudaGetSymbolAddress((void**)&a_p, g_att);

    const int attn_smem = (QT + 64 + 64 + QT) * FSTR * (int)sizeof(uint32_t); // 104448
    cudaFuncSetAttribute(attn_kernel, cudaFuncAttributeMaxDynamicSharedMemorySize,
                         attn_smem);

    ln_kernel<<<BT, 256>>>(x, g1, b1, h_p);

    dim3 qkv_grid(DIM / 128, BT / 128, 3);
    gemm_qkv<<<qkv_grid, 256>>>(h_p, Wq, bq, q_p, Wk, bk, k_p, Wv, bv, v_p,
                                BT, DIM, DIM);

    attn_kernel<<<dim3(TSEQ / QT, NH, 2), 256, attn_smem>>>(q_p, k_p, v_p, a_p);

    dim3 ggrid(DIM / 128, BT / 128);
    gemm_tf32<<<ggrid, 256>>>(a_p, Wo, bo, out, BT, DIM, DIM);
}

// round 13
// speedup vs baseline: 1.7630x; 1.4196x over previous
#include <cuda_runtime.h>
#include <cuda_fp16.h>
#include <cstdint>

#define DIM 1024
#define NH 16
#define HD 64
#define TSEQ 2048
#define BT 4096          // B * T
#define GSTR 20          // gemm smem stride (words)
#define HSTR 72          // attention smem stride (halfs): 36r mod 32 = 4r -> conflict-free
#define QT 128           // attention query-tile rows

// Scratch (static device arrays; allocation in kernel_launch is forbidden)
__device__ float  g_h[BT * DIM];
__device__ __half g_q[BT * DIM];
__device__ __half g_k[BT * DIM];
__device__ __half g_v[BT * DIM];
__device__ float  g_att[BT * DIM];

// ---------------------------------------------------------------------------
// LayerNorm: one block per row of x [4096, 1024]
// ---------------------------------------------------------------------------
__global__ void ln_kernel(const float* __restrict__ x,
                          const float* __restrict__ gamma,
                          const float* __restrict__ beta,
                          float* __restrict__ out) {
    int row = blockIdx.x;
    const float* xr = x + (size_t)row * DIM;
    float* orow = out + (size_t)row * DIM;
    int t = threadIdx.x;

    float v[4];
    float sum = 0.f, sq = 0.f;
#pragma unroll
    for (int i = 0; i < 4; i++) {
        float val = xr[t + i * 256];
        v[i] = val;
        sum += val;
        sq += val * val;
    }
#pragma unroll
    for (int o = 16; o > 0; o >>= 1) {
        sum += __shfl_xor_sync(0xffffffffu, sum, o);
        sq  += __shfl_xor_sync(0xffffffffu, sq, o);
    }
    __shared__ float s1[8], s2[8];
    if ((t & 31) == 0) { s1[t >> 5] = sum; s2[t >> 5] = sq; }
    __syncthreads();
    float tot = 0.f, totq = 0.f;
#pragma unroll
    for (int i = 0; i < 8; i++) { tot += s1[i]; totq += s2[i]; }
    float mu   = tot * (1.0f / DIM);
    float var  = totq * (1.0f / DIM) - mu * mu;
    float rstd = rsqrtf(var + 1e-5f);
#pragma unroll
    for (int i = 0; i < 4; i++) {
        int c = t + i * 256;
        orow[c] = (v[i] - mu) * rstd * gamma[c] + beta[c];
    }
}

// ---------------------------------------------------------------------------
// helpers
// ---------------------------------------------------------------------------
__device__ __forceinline__ uint32_t f2tf(float x) {
    uint32_t y;
    asm("cvt.rna.tf32.f32 %0, %1;" : "=r"(y) : "f"(x));
    return y;
}

__device__ __forceinline__ uint32_t pack_h2(float a, float b) {
    __half2 h = __floats2half2_rn(a, b);
    return *reinterpret_cast<uint32_t*>(&h);
}

__device__ __forceinline__ void mma_tf32(float* c, const uint32_t* a,
                                         const uint32_t* b) {
    asm volatile(
        "mma.sync.aligned.m16n8k8.row.col.f32.tf32.tf32.f32 "
        "{%0,%1,%2,%3}, {%4,%5,%6,%7}, {%8,%9}, {%0,%1,%2,%3};\n"
        : "+f"(c[0]), "+f"(c[1]), "+f"(c[2]), "+f"(c[3])
        : "r"(a[0]), "r"(a[1]), "r"(a[2]), "r"(a[3]), "r"(b[0]), "r"(b[1]));
}

__device__ __forceinline__ void mma_f16(float* c, const uint32_t* a,
                                        const uint32_t* b) {
    asm volatile(
        "mma.sync.aligned.m16n8k16.row.col.f32.f16.f16.f32 "
        "{%0,%1,%2,%3}, {%4,%5,%6,%7}, {%8,%9}, {%0,%1,%2,%3};\n"
        : "+f"(c[0]), "+f"(c[1]), "+f"(c[2]), "+f"(c[3])
        : "r"(a[0]), "r"(a[1]), "r"(a[2]), "r"(a[3]), "r"(b[0]), "r"(b[1]));
}

__device__ __forceinline__ void ldsm_x4(uint32_t& r0, uint32_t& r1,
                                        uint32_t& r2, uint32_t& r3,
                                        uint32_t addr) {
    asm volatile(
        "ldmatrix.sync.aligned.m8n8.x4.shared.b16 {%0,%1,%2,%3}, [%4];"
        : "=r"(r0), "=r"(r1), "=r"(r2), "=r"(r3) : "r"(addr));
}

__device__ __forceinline__ void ldsm_x4_t(uint32_t& r0, uint32_t& r1,
                                          uint32_t& r2, uint32_t& r3,
                                          uint32_t addr) {
    asm volatile(
        "ldmatrix.sync.aligned.m8n8.x4.trans.shared.b16 {%0,%1,%2,%3}, [%4];"
        : "=r"(r0), "=r"(r1), "=r"(r2), "=r"(r3) : "r"(addr));
}

__device__ __forceinline__ void store_pair(float* C, size_t idx, float x, float y) {
    float2 v; v.x = x; v.y = y;
    *(float2*)&C[idx] = v;
}
__device__ __forceinline__ void store_pair(__half* C, size_t idx, float x, float y) {
    *(__half2*)&C[idx] = __floats2half2_rn(x, y);
}

// ---------------------------------------------------------------------------
// tf32 GEMM NT: 128x128 block, 256 threads = 8 warps (2m x 4n), warp tile
// 64x32, BK=16, 2-stage double buffer, ldmatrix fragment loads. (frozen R9/R10)
// Output type templated: float (O-proj) or __half (QKV for fp16 attention).
// ---------------------------------------------------------------------------
template <typename OUT>
__device__ __forceinline__ void gemm_tf32_body(const float* __restrict__ A,
                                               const float* __restrict__ B,
                                               const float* __restrict__ bias,
                                               OUT* __restrict__ C,
                                               int M, int N, int K) {
    __shared__ uint32_t As[2][128 * GSTR];
    __shared__ uint32_t Bs[2][128 * GSTR];

    int tid = threadIdx.x;
    int bm = blockIdx.y * 128;
    int bn = blockIdx.x * 128;
    int w = tid >> 5, lane = tid & 31;
    int wm = (w & 1) * 64;
    int wn = (w >> 1) * 32;
    int lq = lane >> 2;
    int lrm = lane & 3;
    int lr = tid >> 2;
    int lc = (tid & 3) << 2;

    const float* Ap = A + (size_t)(bm + lr) * K + lc;
    const float* Bp = B + (size_t)(bn + lr) * K + lc;

    int g = lane >> 3;
    int lr8 = lane & 7;
    uint32_t aBase = (uint32_t)__cvta_generic_to_shared(&As[0][0]);
    uint32_t bBase = (uint32_t)__cvta_generic_to_shared(&Bs[0][0]);
    const uint32_t stageBytes = 128 * GSTR * 4;
    uint32_t aOff = ((uint32_t)(wm + (g & 1) * 8 + lr8) * GSTR + (g >> 1) * 4) * 4;
    uint32_t bOff = ((uint32_t)(wn + (g >> 1) * 8 + lr8) * GSTR + (g & 1) * 4) * 4;

    float acc[4][4][4];
#pragma unroll
    for (int mi = 0; mi < 4; mi++)
#pragma unroll
        for (int ni = 0; ni < 4; ni++)
#pragma unroll
            for (int r = 0; r < 4; r++) acc[mi][ni][r] = 0.f;

    {
        float4 a0 = *(const float4*)(Ap);
        float4 a1 = *(const float4*)(Ap + (size_t)64 * K);
        float4 b0 = *(const float4*)(Bp);
        float4 b1 = *(const float4*)(Bp + (size_t)64 * K);
        uint4 u;
        u.x = f2tf(a0.x); u.y = f2tf(a0.y); u.z = f2tf(a0.z); u.w = f2tf(a0.w);
        *(uint4*)&As[0][lr * GSTR + lc] = u;
        u.x = f2tf(a1.x); u.y = f2tf(a1.y); u.z = f2tf(a1.z); u.w = f2tf(a1.w);
        *(uint4*)&As[0][(lr + 64) * GSTR + lc] = u;
        u.x = f2tf(b0.x); u.y = f2tf(b0.y); u.z = f2tf(b0.z); u.w = f2tf(b0.w);
        *(uint4*)&Bs[0][lr * GSTR + lc] = u;
        u.x = f2tf(b1.x); u.y = f2tf(b1.y); u.z = f2tf(b1.z); u.w = f2tf(b1.w);
        *(uint4*)&Bs[0][(lr + 64) * GSTR + lc] = u;
    }
    __syncthreads();

    int stage = 0;
    for (int k0 = 0; k0 < K; k0 += 16) {
        int nxt = stage ^ 1;
        bool has_next = (k0 + 16) < K;

        float4 a0, a1, b0, b1;
        if (has_next) {
            a0 = *(const float4*)(Ap + k0 + 16);
            a1 = *(const float4*)(Ap + (size_t)64 * K + k0 + 16);
            b0 = *(const float4*)(Bp + k0 + 16);
            b1 = *(const float4*)(Bp + (size_t)64 * K + k0 + 16);
        }

        uint32_t aS = aBase + stage * stageBytes + aOff;
        uint32_t bS = bBase + stage * stageBytes + bOff;
#pragma unroll
        for (int ks = 0; ks < 16; ks += 8) {
            uint32_t af[4][4];
#pragma unroll
            for (int mi = 0; mi < 4; mi++)
                ldsm_x4(af[mi][0], af[mi][1], af[mi][2], af[mi][3],
                        aS + (uint32_t)(mi * 16 * GSTR + ks) * 4);
            uint32_t bf[4][2];
#pragma unroll
            for (int np = 0; np < 2; np++) {
                uint32_t r0, r1, r2, r3;
                ldsm_x4(r0, r1, r2, r3,
                        bS + (uint32_t)(np * 16 * GSTR + ks) * 4);
                bf[2 * np][0] = r0; bf[2 * np][1] = r1;
                bf[2 * np + 1][0] = r2; bf[2 * np + 1][1] = r3;
            }
#pragma unroll
            for (int mi = 0; mi < 4; mi++)
#pragma unroll
                for (int ni = 0; ni < 4; ni++)
                    mma_tf32(acc[mi][ni], af[mi], bf[ni]);
        }

        if (has_next) {
            uint4 u;
            u.x = f2tf(a0.x); u.y = f2tf(a0.y); u.z = f2tf(a0.z); u.w = f2tf(a0.w);
            *(uint4*)&As[nxt][lr * GSTR + lc] = u;
            u.x = f2tf(a1.x); u.y = f2tf(a1.y); u.z = f2tf(a1.z); u.w = f2tf(a1.w);
            *(uint4*)&As[nxt][(lr + 64) * GSTR + lc] = u;
            u.x = f2tf(b0.x); u.y = f2tf(b0.y); u.z = f2tf(b0.z); u.w = f2tf(b0.w);
            *(uint4*)&Bs[nxt][lr * GSTR + lc] = u;
            u.x = f2tf(b1.x); u.y = f2tf(b1.y); u.z = f2tf(b1.z); u.w = f2tf(b1.w);
            *(uint4*)&Bs[nxt][(lr + 64) * GSTR + lc] = u;
            __syncthreads();
        }
        stage = nxt;
    }

#pragma unroll
    for (int mi = 0; mi < 4; mi++) {
#pragma unroll
        for (int ni = 0; ni < 4; ni++) {
            int row0 = bm + wm + mi * 16 + lq;
            int col  = bn + wn + ni * 8 + lrm * 2;
            float2 bb = *(const float2*)&bias[col];
            store_pair(C, (size_t)row0 * N + col,
                       acc[mi][ni][0] + bb.x, acc[mi][ni][1] + bb.y);
            store_pair(C, (size_t)(row0 + 8) * N + col,
                       acc[mi][ni][2] + bb.x, acc[mi][ni][3] + bb.y);
        }
    }
}

__global__ __launch_bounds__(256) void gemm_tf32(const float* __restrict__ A,
                                                 const float* __restrict__ B,
                                                 const float* __restrict__ bias,
                                                 float* __restrict__ C,
                                                 int M, int N, int K) {
    gemm_tf32_body<float>(A, B, bias, C, M, N, K);
}

// Fused QKV GEMM with fp16 outputs for the attention kernel
__global__ __launch_bounds__(256) void gemm_qkv(const float* __restrict__ A,
                                                const float* __restrict__ Wq,
                                                const float* __restrict__ bq,
                                                __half* __restrict__ Oq,
                                                const float* __restrict__ Wk,
                                                const float* __restrict__ bk,
                                                __half* __restrict__ Ok,
                                                const float* __restrict__ Wv,
                                                const float* __restrict__ bv,
                                                __half* __restrict__ Ov,
                                                int M, int N, int K) {
    int z = blockIdx.z;
    const float* W = (z == 0) ? Wq : (z == 1) ? Wk : Wv;
    const float* b = (z == 0) ? bq : (z == 1) ? bk : bv;
    __half* O      = (z == 0) ? Oq : (z == 1) ? Ok : Ov;
    gemm_tf32_body<__half>(A, W, b, O, M, N, K);
}

// ---------------------------------------------------------------------------
// fp16 tensor-core causal flash attention (FA2-style), 128-row Q tile.
// Grid: (T/128, NH, B). Block: 256 threads = 8 warps; warp w owns q rows
// [16w, 16w+16). 64-key tiles. S and PV via mma.sync.m16n8k16 f16 (fp32 acc).
// P stays in registers (C-frag == A-frag layout for fp16).
// V loaded row-major; B-fragments via ldmatrix.trans.
// ---------------------------------------------------------------------------
__global__ __launch_bounds__(256) void attn_kernel(const __half* __restrict__ Q,
                                                   const __half* __restrict__ K,
                                                   const __half* __restrict__ V,
                                                   float* __restrict__ O) {
    __shared__ __half sQ[QT * HSTR];
    __shared__ __half sK[64 * HSTR];
    __shared__ __half sV[64 * HSTR];

    int tid = threadIdx.x;
    int w = tid >> 5, lane = tid & 31;
    int lq = lane >> 2, lrm = lane & 3;
    int rowA = w * 16;
    int qblk = blockIdx.x;
    int h = blockIdx.y;
    int b = blockIdx.z;
    int q0 = qblk * QT;
    size_t base = ((size_t)b * TSEQ) * DIM + h * HD;

    // loader mappings (halfs)
    int qlr = tid >> 1;             // 0..127
    int qlc = (tid & 1) * 32;       // 0/32
    int klr = tid & 63;             // 0..63
    int klc = (tid >> 6) * 16;      // 0,16,32,48

    // ldmatrix lane addressing (byte offsets; HSTR halfs * 2 bytes)
    int g = lane >> 3;
    int lr8 = lane & 7;
    uint32_t qBase = (uint32_t)__cvta_generic_to_shared(sQ);
    uint32_t kBase = (uint32_t)__cvta_generic_to_shared(sK);
    uint32_t vBase = (uint32_t)__cvta_generic_to_shared(sV);
    // A-frag (sQ): g&1 -> +8 rows, g>>1 -> +8 k-halfs
    uint32_t aOff = ((uint32_t)((rowA + (g & 1) * 8 + lr8) * HSTR) + (g >> 1) * 8) * 2;
    // B-frag (sK, non-trans): rows = keys: g>>1 -> +8 keys; g&1 -> +8 d-halfs
    uint32_t kOff = ((uint32_t)(((g >> 1) * 8 + lr8) * HSTR) + (g & 1) * 8) * 2;
    // B-frag (sV, trans): rows = keys: g&1 -> +8 keys; g>>1 -> +8 d-halfs
    uint32_t vOff = ((uint32_t)(((g & 1) * 8 + lr8) * HSTR) + (g >> 1) * 8) * 2;

    // Load Q tile once (fp16 copy, 32 halfs per thread)
    {
        const uint4* src = (const uint4*)(Q + base + (size_t)(q0 + qlr) * DIM + qlc);
        uint4* dst = (uint4*)(sQ + qlr * HSTR + qlc);
#pragma unroll
        for (int i = 0; i < 4; i++) dst[i] = src[i];
    }

    float o_frag[8][4];
#pragma unroll
    for (int n = 0; n < 8; n++)
#pragma unroll
        for (int r = 0; r < 4; r++) o_frag[n][r] = 0.f;
    float m0 = -1e30f, m1 = -1e30f, l0 = 0.f, l1 = 0.f;

    int kb_max = 2 * qblk + 1;
    for (int kb = 0; kb <= kb_max; kb++) {
        __syncthreads();
        {
            const uint4* ks = (const uint4*)(K + base + (size_t)(kb * 64 + klr) * DIM + klc);
            const uint4* vs = (const uint4*)(V + base + (size_t)(kb * 64 + klr) * DIM + klc);
            uint4* kd = (uint4*)(sK + klr * HSTR + klc);
            uint4* vd = (uint4*)(sV + klr * HSTR + klc);
            kd[0] = ks[0]; kd[1] = ks[1];
            vd[0] = vs[0]; vd[1] = vs[1];
        }
        __syncthreads();

        if (kb * 64 > q0 + rowA + 15) continue;   // fully masked, warp-uniform

        // ---- S = Q K^T : 4 d-chunks of 16, 8 key-tiles of 8 ----
        float s_frag[8][4];
#pragma unroll
        for (int n = 0; n < 8; n++)
#pragma unroll
            for (int r = 0; r < 4; r++) s_frag[n][r] = 0.f;

#pragma unroll
        for (int kc = 0; kc < 4; kc++) {
            uint32_t af[4];
            ldsm_x4(af[0], af[1], af[2], af[3], qBase + aOff + (uint32_t)(kc * 16) * 2);
            uint32_t bf[8][2];
#pragma unroll
            for (int np = 0; np < 4; np++) {
                uint32_t r0, r1, r2, r3;
                ldsm_x4(r0, r1, r2, r3,
                        kBase + kOff + (uint32_t)(np * 16 * HSTR + kc * 16) * 2);
                bf[2 * np][0] = r0; bf[2 * np][1] = r1;
                bf[2 * np + 1][0] = r2; bf[2 * np + 1][1] = r3;
            }
#pragma unroll
            for (int n = 0; n < 8; n++)
                mma_f16(s_frag[n], af, bf[n]);
        }
#pragma unroll
        for (int n = 0; n < 8; n++)
#pragma unroll
            for (int r = 0; r < 4; r++) s_frag[n][r] *= 0.125f;

        // causal mask (global indices) on partially masked tiles
        if (kb * 64 + 63 > q0 + rowA) {
            int r0 = q0 + rowA + lq, r1 = q0 + rowA + lq + 8;
            int cbase = kb * 64;
#pragma unroll
            for (int n = 0; n < 8; n++) {
                int c = cbase + 8 * n + 2 * lrm;
                if (c > r0)     s_frag[n][0] = -1e30f;
                if (c + 1 > r0) s_frag[n][1] = -1e30f;
                if (c > r1)     s_frag[n][2] = -1e30f;
                if (c + 1 > r1) s_frag[n][3] = -1e30f;
            }
        }

        // ---- online softmax on fragments ----
        {
            float mloc0 = -1e30f, mloc1 = -1e30f;
#pragma unroll
            for (int n = 0; n < 8; n++) {
                mloc0 = fmaxf(mloc0, fmaxf(s_frag[n][0], s_frag[n][1]));
                mloc1 = fmaxf(mloc1, fmaxf(s_frag[n][2], s_frag[n][3]));
            }
            mloc0 = fmaxf(mloc0, __shfl_xor_sync(0xffffffffu, mloc0, 1));
            mloc0 = fmaxf(mloc0, __shfl_xor_sync(0xffffffffu, mloc0, 2));
            mloc1 = fmaxf(mloc1, __shfl_xor_sync(0xffffffffu, mloc1, 1));
            mloc1 = fmaxf(mloc1, __shfl_xor_sync(0xffffffffu, mloc1, 2));
            float mn0 = fmaxf(m0, mloc0), mn1 = fmaxf(m1, mloc1);
            float c0 = __expf(m0 - mn0), c1 = __expf(m1 - mn1);
            float ps0 = 0.f, ps1 = 0.f;
#pragma unroll
            for (int n = 0; n < 8; n++) {
                float p0 = __expf(s_frag[n][0] - mn0);
                float p1 = __expf(s_frag[n][1] - mn0);
                float p2 = __expf(s_frag[n][2] - mn1);
                float p3 = __expf(s_frag[n][3] - mn1);
                s_frag[n][0] = p0; s_frag[n][1] = p1;
                s_frag[n][2] = p2; s_frag[n][3] = p3;
                ps0 += p0 + p1; ps1 += p2 + p3;
            }
            ps0 += __shfl_xor_sync(0xffffffffu, ps0, 1);
            ps0 += __shfl_xor_sync(0xffffffffu, ps0, 2);
            ps1 += __shfl_xor_sync(0xffffffffu, ps1, 1);
            ps1 += __shfl_xor_sync(0xffffffffu, ps1, 2);
            l0 = l0 * c0 + ps0; m0 = mn0;
            l1 = l1 * c1 + ps1; m1 = mn1;
#pragma unroll
            for (int n = 0; n < 8; n++) {
                o_frag[n][0] *= c0; o_frag[n][1] *= c0;
                o_frag[n][2] *= c1; o_frag[n][3] *= c1;
            }
        }

        // ---- O += P V : P from registers (C-frag == A-frag for fp16) ----
#pragma unroll
        for (int j = 0; j < 4; j++) {     // key chunks of 16
            uint32_t ap[4];
            ap[0] = pack_h2(s_frag[2 * j][0], s_frag[2 * j][1]);
            ap[1] = pack_h2(s_frag[2 * j][2], s_frag[2 * j][3]);
            ap[2] = pack_h2(s_frag[2 * j + 1][0], s_frag[2 * j + 1][1]);
            ap[3] = pack_h2(s_frag[2 * j + 1][2], s_frag[2 * j + 1][3]);
            uint32_t bf[8][2];
#pragma unroll
            for (int np = 0; np < 4; np++) {
                uint32_t r0, r1, r2, r3;
                ldsm_x4_t(r0, r1, r2, r3,
                          vBase + vOff + (uint32_t)(j * 16 * HSTR + np * 16) * 2);
                bf[2 * np][0] = r0; bf[2 * np][1] = r1;
                bf[2 * np + 1][0] = r2; bf[2 * np + 1][1] = r3;
            }
#pragma unroll
            for (int n = 0; n < 8; n++)
                mma_f16(o_frag[n], ap, bf[n]);
        }
    }

    float i0 = 1.0f / l0, i1 = 1.0f / l1;
    float* d0 = O + base + (size_t)(q0 + rowA + lq) * DIM;
    float* d1 = O + base + (size_t)(q0 + rowA + lq + 8) * DIM;
#pragma unroll
    for (int n = 0; n < 8; n++) {
        int col = 8 * n + 2 * lrm;
        float2 w0; w0.x = o_frag[n][0] * i0; w0.y = o_frag[n][1] * i0;
        float2 w1; w1.x = o_frag[n][2] * i1; w1.y = o_frag[n][3] * i1;
        *(float2*)&d0[col] = w0;
        *(float2*)&d1[col] = w1;
    }
}

// ---------------------------------------------------------------------------
extern "C" void kernel_launch(void* const* d_in, const int* in_sizes, int n_in,
                              void* d_out, int out_size) {
    const float* x  = (const float*)d_in[0];
    const float* g1 = (const float*)d_in[1];
    const float* b1 = (const float*)d_in[2];
    const float* Wq = (const float*)d_in[3];
    const float* bq = (const float*)d_in[4];
    const float* Wk = (const float*)d_in[5];
    const float* bk = (const float*)d_in[6];
    const float* Wv = (const float*)d_in[7];
    const float* bv = (const float*)d_in[8];
    const float* Wo = (const float*)d_in[9];
    const float* bo = (const float*)d_in[10];
    float* out = (float*)d_out;

    float *h_p, *a_p;
    __half *q_p, *k_p, *v_p;
    cudaGetSymbolAddress((void**)&h_p, g_h);
    cudaGetSymbolAddress((void**)&q_p, g_q);
    cudaGetSymbolAddress((void**)&k_p, g_k);
    cudaGetSymbolAddress((void**)&v_p, g_v);
    cudaGetSymbolAddress((void**)&a_p, g_att);

    ln_kernel<<<BT, 256>>>(x, g1, b1, h_p);

    dim3 qkv_grid(DIM / 128, BT / 128, 3);
    gemm_qkv<<<qkv_grid, 256>>>(h_p, Wq, bq, q_p, Wk, bk, k_p, Wv, bv, v_p,
                                BT, DIM, DIM);

    attn_kernel<<<dim3(TSEQ / QT, NH, 2), 256>>>(q_p, k_p, v_p, a_p);

    dim3 ggrid(DIM / 128, BT / 128);
    gemm_tf32<<<ggrid, 256>>>(a_p, Wo, bo, out, BT, DIM, DIM);
}